// round 3
// baseline (speedup 1.0000x reference)
#include <cuda_runtime.h>

// Problem: N=65536 rows. Per row n:
//   m = max_k |dot(x[n,k,:], y[n,0,:])|   (K=1024, D=4)
//   if m > 0.9999999 -> m = 1.0   (cost >= 0, so LOWER clamp is dead)
//   d[n] = 2*acos(m)              (acos monotone decreasing => min over k of
//                                  2*acos(cost) == 2*acos(max_k cost))
// out = sum(d) / N
//
// Inputs (metadata order): d_in[0]=y (N,1,4) f32, d_in[1]=w_y (N,K) f32 (UNUSED),
//                          d_in[2]=x (N,K,4) f32. Output: 1 f32 scalar.
//
// Persistent single-wave kernel: grid = 148 SMs x 8 resident blocks. Each
// block grid-strides over row-groups (8 rows per block-iteration),
// accumulating its d-sum locally; one partial per block; last arriving block
// (ticket) reduces 1184 partials in fixed order -> deterministic.

#define N_ROWS   65536
#define K_DIM    1024
#define WARPS_PER_BLOCK 8
#define THREADS  (WARPS_PER_BLOCK * 32)
#define NGROUPS  (N_ROWS / WARPS_PER_BLOCK)   // 8192 row-groups of 8 rows
#define NSM      148
#define BLOCKS_PER_SM 8
#define GRID     (NSM * BLOCKS_PER_SM)        // 1184 persistent blocks

__device__ float        g_partials[GRID];
__device__ unsigned int g_ticket = 0;          // self-resetting each launch

__global__ __launch_bounds__(THREADS, BLOCKS_PER_SM)
void fused_kernel(const float* __restrict__ y,
                  const float* __restrict__ x,
                  float* __restrict__ out)
{
    const int warp_in_blk = threadIdx.x >> 5;
    const int lane        = threadIdx.x & 31;

    float d_acc = 0.0f;   // meaningful on lane 0 of each warp

    // grid-stride over row groups; fixed assignment -> deterministic
    for (int grp = blockIdx.x; grp < NGROUPS; grp += GRID) {
        const int n = grp * WARPS_PER_BLOCK + warp_in_blk;

        const float4 y0 = reinterpret_cast<const float4*>(y)[n];
        const float4* xp = reinterpret_cast<const float4*>(x) + (size_t)n * K_DIM;

        float m = 0.0f;
        #pragma unroll 8
        for (int i = 0; i < K_DIM / 32; ++i) {
            float4 v = __ldcs(&xp[lane + 32 * i]);   // streamed once
            float dot = fabsf(v.x * y0.x + v.y * y0.y + v.z * y0.z + v.w * y0.w);
            m = fmaxf(m, dot);
        }

        #pragma unroll
        for (int off = 16; off > 0; off >>= 1)
            m = fmaxf(m, __shfl_xor_sync(0xFFFFFFFFu, m, off));

        if (lane == 0) {
            if (m > 0.9999999f) m = 1.0f;
            d_acc += 2.0f * acosf(m);
        }
    }

    // block reduction of the 8 warp accumulators
    __shared__ float s_d[WARPS_PER_BLOCK];
    if (lane == 0) s_d[warp_in_blk] = d_acc;
    __syncthreads();

    __shared__ bool s_last;
    if (threadIdx.x == 0) {
        float t = 0.0f;
        #pragma unroll
        for (int i = 0; i < WARPS_PER_BLOCK; ++i) t += s_d[i];
        g_partials[blockIdx.x] = t;
        __threadfence();                               // publish partial
        unsigned int tk = atomicAdd(&g_ticket, 1u);
        s_last = (tk == GRID - 1);
    }
    __syncthreads();

    if (!s_last) return;

    // ---- last block: deterministic final reduction over g_partials ----
    const int tid = threadIdx.x;
    float t = 0.0f;
    #pragma unroll
    for (int i = tid; i < GRID; i += THREADS)
        t += __ldcg(&g_partials[i]);                   // L2-coherent read

    #pragma unroll
    for (int off = 16; off > 0; off >>= 1)
        t += __shfl_xor_sync(0xFFFFFFFFu, t, off);

    __shared__ float s_w[WARPS_PER_BLOCK];
    if (lane == 0) s_w[warp_in_blk] = t;
    __syncthreads();

    if (tid == 0) {
        float v = 0.0f;
        #pragma unroll
        for (int i = 0; i < WARPS_PER_BLOCK; ++i) v += s_w[i];
        out[0] = v / (float)N_ROWS;
        g_ticket = 0;                                  // reset for next replay
    }
}

extern "C" void kernel_launch(void* const* d_in, const int* in_sizes, int n_in,
                              void* d_out, int out_size)
{
    const float* y = (const float*)d_in[0];
    // d_in[1] = w_y : unused by the reference reduction
    const float* x = (const float*)d_in[2];
    float* out = (float*)d_out;

    fused_kernel<<<GRID, THREADS>>>(y, x, out);
}

// round 4
// speedup vs baseline: 1.0237x; 1.0237x over previous
#include <cuda_runtime.h>

// Problem: N=65536 rows. Per row n:
//   m = max_k |dot(x[n,k,:], y[n,0,:])|   (K=1024, D=4)
//   if m > 0.9999999 -> m = 1.0   (cost >= 0, so LOWER clamp is dead)
//   d[n] = 2*acos(m)              (acos monotone decreasing => min over k of
//                                  2*acos(cost) == 2*acos(max_k cost))
// out = sum(d) / N
//
// Inputs: d_in[0]=y (N,1,4) f32, d_in[1]=w_y (UNUSED), d_in[2]=x (N,K,4) f32.
// Output: 1 f32 scalar.
//
// R2 structure (8192 blocks, HW-scheduled waves — measured fastest) plus a
// hierarchical two-level ticket reduction so the serial tail shrinks from
// 8192 partials to 128 group sums. Group reductions overlap with streaming
// of later waves. Deterministic: fixed groups, fixed summation order.

#define N_ROWS   65536
#define K_DIM    1024
#define WARPS_PER_BLOCK 8
#define THREADS  (WARPS_PER_BLOCK * 32)
#define NBLOCKS  (N_ROWS / WARPS_PER_BLOCK)   // 8192
#define GROUP_SZ 64
#define NGROUPS  (NBLOCKS / GROUP_SZ)          // 128

__device__ float        g_partials[NBLOCKS];
__device__ float        g_groupsum[NGROUPS];
__device__ unsigned int g_group_ticket[NGROUPS];  // zero-init; self-resetting
__device__ unsigned int g_ticket = 0;             // self-resetting

__global__ __launch_bounds__(THREADS)
void fused_kernel(const float* __restrict__ y,
                  const float* __restrict__ x,
                  float* __restrict__ out)
{
    const int warp_in_blk = threadIdx.x >> 5;
    const int lane        = threadIdx.x & 31;
    const int n           = blockIdx.x * WARPS_PER_BLOCK + warp_in_blk;

    // y0 for this row: all lanes of the warp read the same float4 (broadcast)
    const float4 y0 = reinterpret_cast<const float4*>(y)[n];

    const float4* xp = reinterpret_cast<const float4*>(x) + (size_t)n * K_DIM;

    float m = 0.0f;
    #pragma unroll 8
    for (int i = 0; i < K_DIM / 32; ++i) {
        float4 v = __ldcs(&xp[lane + 32 * i]);   // streamed once: evict-first
        float dot = fabsf(v.x * y0.x + v.y * y0.y + v.z * y0.z + v.w * y0.w);
        m = fmaxf(m, dot);
    }

    // warp max-reduce
    #pragma unroll
    for (int off = 16; off > 0; off >>= 1)
        m = fmaxf(m, __shfl_xor_sync(0xFFFFFFFFu, m, off));

    __shared__ float s_d[WARPS_PER_BLOCK];
    if (lane == 0) {
        if (m > 0.9999999f) m = 1.0f;
        s_d[warp_in_blk] = 2.0f * acosf(m);
    }
    __syncthreads();

    // ---- level 1: publish block partial; last-in-group reduces 64 partials
    const int grp = blockIdx.x / GROUP_SZ;
    __shared__ bool s_group_last;
    if (threadIdx.x == 0) {
        float t = 0.0f;
        #pragma unroll
        for (int i = 0; i < WARPS_PER_BLOCK; ++i) t += s_d[i];
        g_partials[blockIdx.x] = t;
        __threadfence();
        unsigned int tk = atomicAdd(&g_group_ticket[grp], 1u);
        s_group_last = (tk == GROUP_SZ - 1);
    }
    __syncthreads();
    if (!s_group_last) return;

    // one warp reduces this group's 64 partials in fixed order
    __shared__ bool s_last;
    if (threadIdx.x < 32) {
        const int base = grp * GROUP_SZ;
        float t = __ldcg(&g_partials[base + lane]) +
                  __ldcg(&g_partials[base + 32 + lane]);
        #pragma unroll
        for (int off = 16; off > 0; off >>= 1)
            t += __shfl_xor_sync(0xFFFFFFFFu, t, off);
        if (lane == 0) {
            g_groupsum[grp] = t;
            g_group_ticket[grp] = 0;                   // reset for next replay
            __threadfence();
            unsigned int tk = atomicAdd(&g_ticket, 1u);
            s_last = (tk == NGROUPS - 1);
        }
    }
    __syncthreads();
    if (!s_last) return;

    // ---- level 2: very last block reduces 128 group sums (fixed order)
    if (threadIdx.x < 32) {
        float t = __ldcg(&g_groupsum[lane]) +
                  __ldcg(&g_groupsum[32 + lane]) +
                  __ldcg(&g_groupsum[64 + lane]) +
                  __ldcg(&g_groupsum[96 + lane]);
        #pragma unroll
        for (int off = 16; off > 0; off >>= 1)
            t += __shfl_xor_sync(0xFFFFFFFFu, t, off);
        if (lane == 0) {
            out[0] = t / (float)N_ROWS;
            g_ticket = 0;                              // reset for next replay
        }
    }
}

extern "C" void kernel_launch(void* const* d_in, const int* in_sizes, int n_in,
                              void* d_out, int out_size)
{
    const float* y = (const float*)d_in[0];
    // d_in[1] = w_y : unused by the reference reduction
    const float* x = (const float*)d_in[2];
    float* out = (float*)d_out;

    fused_kernel<<<NBLOCKS, THREADS>>>(y, x, out);
}